// round 13
// baseline (speedup 1.0000x reference)
#include <cuda_runtime.h>

// Problem constants (AdaBIGGAN last adaptive stage)
#define BB 32
#define CC 96
#define HH 128
#define WW 128
#define INF 148               // hypernet input dim

#define HW  (HH * WW)         // 16384 floats per (b,c) plane
#define HW4 (HW / 4)          // 4096 float4 per plane

#define NGRP 4                       // row-groups per channel
#define ROWS_PER_GRP (CC / NGRP)     // 24
#define NPROD (CC * NGRP)            // 384 producer blocks
#define GRID_X (HW4 / 1024)          // 4
#define TOTAL_BLOCKS (GRID_X * BB * CC)   // 12288

// Scratch + sync state (no cudaMalloc allowed)
__device__ float        g_part [NPROD * INF];   // partial column sums of Wg_w
__device__ float        g_bpart[NPROD];         // partial sums of Wg_b
__device__ unsigned int g_done     = 0;         // producers finished
__device__ unsigned int g_consumed = 0;         // blocks finished (reset logic)

// ---------------------------------------------------------------------------
// Single fused kernel, producer-FIRST ordering.
// Producers = linear blocks 0..383 (wave-1 residents at occ>=8/SM). They run
// their Wg_w/Wg_b slice reduction BEFORE touching h, so their loads are not
// queued behind the grid's streaming loads, then release g_done and fall
// through to their own streaming work. Consumers front-batch 4 h-loads
// (prefetch), poll g_done with a volatile read + nanosleep, then do the
// per-(b,c) dot and the stream. Last block resets counters (replay-safe).
// ---------------------------------------------------------------------------
__global__ __launch_bounds__(256) void fused_kernel(
    const float* __restrict__ h,
    const float* __restrict__ y,      // [B, IN]
    const float* __restrict__ Wg_w,   // [C*C, IN]
    const float* __restrict__ Wg_b,   // [C*C]
    const float* __restrict__ Bg_w,   // [C, IN]
    const float* __restrict__ Bg_b,   // [C]
    float* __restrict__ out)
{
    const int bc     = blockIdx.y;        // b*CC + c
    const int c      = bc % CC;
    const int b      = bc / CC;
    const int tid    = threadIdx.x;
    const int linear = blockIdx.x + GRID_X * blockIdx.y;
    const bool is_producer = (linear < NPROD);

    const float4* __restrict__ hp = reinterpret_cast<const float4*>(h  + (size_t)bc * HW);
    float4*       __restrict__ op = reinterpret_cast<float4*>      (out + (size_t)bc * HW);
    const int base = blockIdx.x * 1024 + tid;

    float4 v0, v1, v2, v3;

    if (is_producer) {
        // ---- produce FIRST: slice reduction goes to the head of the queue ----
        const int pc = linear >> 2;       // channel
        const int pg = linear & 3;        // row group
        const float* pbase = Wg_w + ((size_t)pc * CC + pg * ROWS_PER_GRP) * INF;

        if (tid < INF) {
            float s = 0.f;
            #pragma unroll
            for (int r = 0; r < ROWS_PER_GRP; ++r)
                s += __ldg(pbase + (size_t)r * INF + tid);
            g_part[linear * INF + tid] = s;
        }
        if (tid >= 192 && tid < 224) {    // one warp for the Wg_b partial
            const int l = tid - 192;
            float pb = (l < ROWS_PER_GRP)
                     ? __ldg(Wg_b + pc * CC + pg * ROWS_PER_GRP + l) : 0.f;
            #pragma unroll
            for (int o = 16; o > 0; o >>= 1)
                pb += __shfl_down_sync(0xffffffffu, pb, o);
            if (l == 0) g_bpart[linear] = pb;
        }
        __syncthreads();
        if (tid == 0) {
            __threadfence();              // release g_part/g_bpart
            atomicAdd(&g_done, 1u);
        }
        // now start this block's own streaming loads
        v0 = __ldcs(hp + base);
        v1 = __ldcs(hp + base + 256);
        v2 = __ldcs(hp + base + 512);
        v3 = __ldcs(hp + base + 768);
    } else {
        // ---- consumers: prefetch the stream, then wait ----
        v0 = __ldcs(hp + base);
        v1 = __ldcs(hp + base + 256);
        v2 = __ldcs(hp + base + 512);
        v3 = __ldcs(hp + base + 768);
    }

    // ---- wait for all producers (cheap volatile poll, tid 0 only) ----
    if (tid == 0) {
        const volatile unsigned int* dp = &g_done;
        while (*dp < (unsigned)NPROD)
            __nanosleep(64);
    }
    __syncthreads();
    __threadfence();                      // acquire: order g_part reads after flag

    // ---- prologue: per-(b,c) scale/bias dot (operands L2-resident) ----
    __shared__ float sh_ds[8], sh_db[8];
    __shared__ float sh_s, sh_b;

    float ds = 0.f, db = 0.f;
    if (tid < INF) {
        const float yv = __ldg(y + b * INF + tid);
        const float* pp = g_part + (size_t)(c * NGRP) * INF + tid;
        const float w = pp[0] + pp[INF] + pp[2 * INF] + pp[3 * INF];
        ds = yv * w;
        db = yv * __ldg(Bg_w + c * INF + tid);
    }
    #pragma unroll
    for (int o = 16; o > 0; o >>= 1) {
        ds += __shfl_down_sync(0xffffffffu, ds, o);
        db += __shfl_down_sync(0xffffffffu, db, o);
    }
    const int warp = tid >> 5, lane = tid & 31;
    if (lane == 0) { sh_ds[warp] = ds; sh_db[warp] = db; }
    __syncthreads();
    if (tid == 0) {
        float S = sh_ds[0] + sh_ds[1] + sh_ds[2] + sh_ds[3]
                + sh_ds[4] + sh_ds[5] + sh_ds[6] + sh_ds[7];
        float D = sh_db[0] + sh_db[1] + sh_db[2] + sh_db[3]
                + sh_db[4] + sh_db[5] + sh_db[6] + sh_db[7];
        const float* bp = g_bpart + c * NGRP;
        S += bp[0] + bp[1] + bp[2] + bp[3];
        D += __ldg(Bg_b + c);
        sh_s = S; sh_b = D;
    }
    __syncthreads();
    const float s  = sh_s;
    const float bi = sh_b;

    // ---- affine + relu + streaming stores ----
    v0.x = fmaxf(fmaf(v0.x, s, bi), 0.f);
    v0.y = fmaxf(fmaf(v0.y, s, bi), 0.f);
    v0.z = fmaxf(fmaf(v0.z, s, bi), 0.f);
    v0.w = fmaxf(fmaf(v0.w, s, bi), 0.f);
    v1.x = fmaxf(fmaf(v1.x, s, bi), 0.f);
    v1.y = fmaxf(fmaf(v1.y, s, bi), 0.f);
    v1.z = fmaxf(fmaf(v1.z, s, bi), 0.f);
    v1.w = fmaxf(fmaf(v1.w, s, bi), 0.f);
    v2.x = fmaxf(fmaf(v2.x, s, bi), 0.f);
    v2.y = fmaxf(fmaf(v2.y, s, bi), 0.f);
    v2.z = fmaxf(fmaf(v2.z, s, bi), 0.f);
    v2.w = fmaxf(fmaf(v2.w, s, bi), 0.f);
    v3.x = fmaxf(fmaf(v3.x, s, bi), 0.f);
    v3.y = fmaxf(fmaf(v3.y, s, bi), 0.f);
    v3.z = fmaxf(fmaf(v3.z, s, bi), 0.f);
    v3.w = fmaxf(fmaf(v3.w, s, bi), 0.f);

    __stcs(op + base,       v0);
    __stcs(op + base + 256, v1);
    __stcs(op + base + 512, v2);
    __stcs(op + base + 768, v3);

    // ---- replay-safe reset handshake ----
    __syncthreads();                      // every thread past its g_done read
    if (tid == 0) {
        const unsigned prev = atomicAdd(&g_consumed, 1u);
        if (prev == (unsigned)(TOTAL_BLOCKS - 1)) {
            atomicExch(&g_done, 0u);      // all blocks have consumed the flag
            atomicExch(&g_consumed, 0u);
        }
    }
}

// ---------------------------------------------------------------------------
// Launch. Input order per metadata: h, y, Wg_w, Wg_b, Bg_w, Bg_b
// ---------------------------------------------------------------------------
extern "C" void kernel_launch(void* const* d_in, const int* in_sizes, int n_in,
                              void* d_out, int out_size)
{
    const float* h    = (const float*)d_in[0];
    const float* y    = (const float*)d_in[1];
    const float* Wg_w = (const float*)d_in[2];
    const float* Wg_b = (const float*)d_in[3];
    const float* Bg_w = (const float*)d_in[4];
    const float* Bg_b = (const float*)d_in[5];
    float* out = (float*)d_out;

    dim3 grid(GRID_X, BB * CC);   // (4, 3072)
    fused_kernel<<<grid, 256>>>(h, y, Wg_w, Wg_b, Bg_w, Bg_b, out);
}

// round 14
// speedup vs baseline: 1.1242x; 1.1242x over previous
#include <cuda_runtime.h>
#include <cooperative_groups.h>

namespace cg = cooperative_groups;

// Problem constants (AdaBIGGAN last adaptive stage)
#define BB 32
#define CC 96
#define HH 128
#define WW 128
#define INF 148               // hypernet input dim

#define HW  (HH * WW)         // 16384 floats per (b,c) plane
#define HW4 (HW / 4)          // 4096 float4 per plane

#define GRID_X 4                     // chunks per (b,c) plane == cluster size
#define ROWS_PER_CTA (CC / GRID_X)   // 24 Wg_w rows per CTA in the dot

// ---------------------------------------------------------------------------
// Single fused kernel, cluster-cooperative scale/bias.
// The 4 CTAs of one (b,c) plane form a cluster. Each CTA:
//   1. front-issues its 4 streaming float4 h-loads,
//   2. computes a 24-row partial of scale = y.(Wg_w rows) + Wg_b rows,
//      and the full bias dot y.Bg_w[c] + Bg_b[c],
//   3. exchanges its scale partial with the 3 peer CTAs via DSMEM,
//   4. cluster.sync(), sums the 4 partials, runs the affine+relu stream.
// No global synchronization anywhere -> stream pipelining stays intact.
// ---------------------------------------------------------------------------
__global__ __launch_bounds__(256) void fused_kernel(
    const float* __restrict__ h,
    const float* __restrict__ y,      // [B, IN]
    const float* __restrict__ Wg_w,   // [C*C, IN]
    const float* __restrict__ Wg_b,   // [C*C]
    const float* __restrict__ Bg_w,   // [C, IN]
    const float* __restrict__ Bg_b,   // [C]
    float* __restrict__ out)
{
    const int bc   = blockIdx.y;          // b*CC + c
    const int c    = bc % CC;
    const int b    = bc / CC;
    const int tid  = threadIdx.x;
    const int warp = tid >> 5;
    const int lane = tid & 31;

    cg::cluster_group cluster = cg::this_cluster();
    const unsigned rank = cluster.block_rank();   // == blockIdx.x

    // ---- 1. front-issue the streaming loads ----
    const float4* __restrict__ hp = reinterpret_cast<const float4*>(h  + (size_t)bc * HW);
    float4*       __restrict__ op = reinterpret_cast<float4*>      (out + (size_t)bc * HW);
    const int base = blockIdx.x * 1024 + tid;

    float4 v0 = __ldcs(hp + base);
    float4 v1 = __ldcs(hp + base + 256);
    float4 v2 = __ldcs(hp + base + 512);
    float4 v3 = __ldcs(hp + base + 768);

    // ---- 2. partial scale dot (my 24 rows) + full bias dot ----
    __shared__ float sh_sw[8];        // per-warp scale partials
    __shared__ float sh_bw[8];        // per-warp bias partials
    __shared__ float slots[GRID_X];   // DSMEM exchange target (scale partials)
    __shared__ float sh_bias;

    const float* yb = y + b * INF;
    // warp w handles rows rank*24 + w*3 .. +2; lanes stride columns.
    const int row0 = (int)rank * ROWS_PER_CTA + warp * 3;
    const float* r0p = Wg_w + (size_t)(c * CC + row0) * INF;

    float acc = 0.f;
    #pragma unroll
    for (int k = 0; k < 5; ++k) {
        const int i = lane + 32 * k;
        if (i < INF) {
            const float yv = yb[i];
            acc = fmaf(yv, r0p[i],            acc);
            acc = fmaf(yv, r0p[INF + i],      acc);
            acc = fmaf(yv, r0p[2 * INF + i],  acc);
        }
    }
    // fold the Wg_b terms for my 3 rows (scale = y.wsum + sum Wg_b)
    if (lane < 3) acc += __ldg(Wg_b + c * CC + row0 + lane);

    // bias dot: thread tid covers column tid (<148)
    float db = 0.f;
    if (tid < INF) db = yb[tid] * __ldg(Bg_w + c * INF + tid);

    #pragma unroll
    for (int o = 16; o > 0; o >>= 1) {
        acc += __shfl_down_sync(0xffffffffu, acc, o);
        db  += __shfl_down_sync(0xffffffffu, db,  o);
    }
    if (lane == 0) { sh_sw[warp] = acc; sh_bw[warp] = db; }
    __syncthreads();

    if (tid == 0) {
        const float ps = sh_sw[0] + sh_sw[1] + sh_sw[2] + sh_sw[3]
                       + sh_sw[4] + sh_sw[5] + sh_sw[6] + sh_sw[7];
        sh_bias = sh_bw[0] + sh_bw[1] + sh_bw[2] + sh_bw[3]
                + sh_bw[4] + sh_bw[5] + sh_bw[6] + sh_bw[7]
                + __ldg(Bg_b + c);
        // ---- 3. broadcast my scale partial to every CTA in the cluster ----
        #pragma unroll
        for (int r = 0; r < GRID_X; ++r) {
            float* dst = (float*)cluster.map_shared_rank(slots, r);
            dst[rank] = ps;
        }
    }

    // ---- 4. cluster barrier, then combine ----
    cluster.sync();

    const float s  = slots[0] + slots[1] + slots[2] + slots[3];
    const float bi = sh_bias;

    // ---- affine + relu + streaming stores ----
    v0.x = fmaxf(fmaf(v0.x, s, bi), 0.f);
    v0.y = fmaxf(fmaf(v0.y, s, bi), 0.f);
    v0.z = fmaxf(fmaf(v0.z, s, bi), 0.f);
    v0.w = fmaxf(fmaf(v0.w, s, bi), 0.f);
    v1.x = fmaxf(fmaf(v1.x, s, bi), 0.f);
    v1.y = fmaxf(fmaf(v1.y, s, bi), 0.f);
    v1.z = fmaxf(fmaf(v1.z, s, bi), 0.f);
    v1.w = fmaxf(fmaf(v1.w, s, bi), 0.f);
    v2.x = fmaxf(fmaf(v2.x, s, bi), 0.f);
    v2.y = fmaxf(fmaf(v2.y, s, bi), 0.f);
    v2.z = fmaxf(fmaf(v2.z, s, bi), 0.f);
    v2.w = fmaxf(fmaf(v2.w, s, bi), 0.f);
    v3.x = fmaxf(fmaf(v3.x, s, bi), 0.f);
    v3.y = fmaxf(fmaf(v3.y, s, bi), 0.f);
    v3.z = fmaxf(fmaf(v3.z, s, bi), 0.f);
    v3.w = fmaxf(fmaf(v3.w, s, bi), 0.f);

    __stcs(op + base,       v0);
    __stcs(op + base + 256, v1);
    __stcs(op + base + 512, v2);
    __stcs(op + base + 768, v3);
}

// ---------------------------------------------------------------------------
// Launch. Input order per metadata: h, y, Wg_w, Wg_b, Bg_w, Bg_b
// Single node, cluster (4,1,1) along the plane-chunk dimension.
// ---------------------------------------------------------------------------
extern "C" void kernel_launch(void* const* d_in, const int* in_sizes, int n_in,
                              void* d_out, int out_size)
{
    const float* h    = (const float*)d_in[0];
    const float* y    = (const float*)d_in[1];
    const float* Wg_w = (const float*)d_in[2];
    const float* Wg_b = (const float*)d_in[3];
    const float* Bg_w = (const float*)d_in[4];
    const float* Bg_b = (const float*)d_in[5];
    float* out = (float*)d_out;

    cudaLaunchConfig_t cfg = {};
    cfg.gridDim  = dim3(GRID_X, BB * CC);   // (4, 3072)
    cfg.blockDim = dim3(256);
    cfg.dynamicSmemBytes = 0;
    cfg.stream = 0;

    cudaLaunchAttribute attr[1];
    attr[0].id = cudaLaunchAttributeClusterDimension;
    attr[0].val.clusterDim = {GRID_X, 1, 1};
    cfg.attrs = attr;
    cfg.numAttrs = 1;

    cudaLaunchKernelEx(&cfg, fused_kernel, h, y, Wg_w, Wg_b, Bg_w, Bg_b, out);
}

// round 15
// speedup vs baseline: 1.1585x; 1.0305x over previous
#include <cuda_runtime.h>

// Problem constants (AdaBIGGAN last adaptive stage)
#define BB 32
#define CC 96
#define HH 128
#define WW 128
#define INF 148               // hypernet input dim

#define HW  (HH * WW)         // 16384 floats per (b,c) plane
#define HW4 (HW / 4)          // 4096 float4 per plane

#define NBLK (BB * CC)        // 3072 blocks, one per (b,c) plane
#define ROWS_PER_WARP (CC / 8)   // 12

// ---------------------------------------------------------------------------
// Single fused kernel, one block per (b,c) plane, ZERO cross-CTA coordination.
// Each block:
//   1. front-issues chunk-0 streaming loads (4 float4/thread),
//   2. computes the full scale dot  s  = y[b] . wsum_c + sum(Wg_b[c,:])
//      (8 warps x 12 rows, lanes stride columns; Wg_w slab is L2-resident)
//      and bias = y[b] . Bg_w[c] + Bg_b[c],
//   3. streams the 16384-float plane in 4 chunks of 4 float4/thread with
//      next-chunk loads issued before current-chunk stores (MLP ~4-8).
// ---------------------------------------------------------------------------
__global__ __launch_bounds__(256) void fused_kernel(
    const float* __restrict__ h,
    const float* __restrict__ y,      // [B, IN]
    const float* __restrict__ Wg_w,   // [C*C, IN]
    const float* __restrict__ Wg_b,   // [C*C]
    const float* __restrict__ Bg_w,   // [C, IN]
    const float* __restrict__ Bg_b,   // [C]
    float* __restrict__ out)
{
    const int bc   = blockIdx.x;          // b*CC + c
    const int c    = bc % CC;
    const int b    = bc / CC;
    const int tid  = threadIdx.x;
    const int warp = tid >> 5;
    const int lane = tid & 31;

    const float4* __restrict__ hp = reinterpret_cast<const float4*>(h  + (size_t)bc * HW);
    float4*       __restrict__ op = reinterpret_cast<float4*>      (out + (size_t)bc * HW);

    // ---- 1. front-issue chunk 0 (goes to DRAM; covers the dot latency) ----
    float4 a0 = __ldcs(op - op + hp + tid);          // hp[tid]
    float4 a1 = __ldcs(hp + tid + 256);
    float4 a2 = __ldcs(hp + tid + 512);
    float4 a3 = __ldcs(hp + tid + 768);

    // ---- 2. full scale/bias dot, block-local ----
    __shared__ float sh_sw[8], sh_bw[8];
    __shared__ float sh_s, sh_b;

    const float* yb = y + b * INF;

    // hoist this lane's 5 y values (columns lane, lane+32, ..., lane+128)
    float y0 = yb[lane];
    float y1 = yb[lane + 32];
    float y2 = yb[lane + 64];
    float y3 = yb[lane + 96];
    float y4 = (lane + 128 < INF) ? yb[lane + 128] : 0.f;

    // warp w handles rows w*12 .. w*12+11 of channel c's slab
    const int row0 = warp * ROWS_PER_WARP;
    const float* wp = Wg_w + (size_t)(c * CC + row0) * INF;

    float acc = 0.f;
    #pragma unroll
    for (int r = 0; r < ROWS_PER_WARP; ++r) {
        const float* rp = wp + (size_t)r * INF;
        acc = fmaf(y0, __ldg(rp + lane),       acc);
        acc = fmaf(y1, __ldg(rp + lane + 32),  acc);
        acc = fmaf(y2, __ldg(rp + lane + 64),  acc);
        acc = fmaf(y3, __ldg(rp + lane + 96),  acc);
        if (lane + 128 < INF)
            acc = fmaf(y4, __ldg(rp + lane + 128), acc);
    }
    // fold Wg_b for this warp's 12 rows into the scale
    if (lane < ROWS_PER_WARP)
        acc += __ldg(Wg_b + c * CC + row0 + lane);

    // bias dot: thread tid covers column tid (<148)
    float db = 0.f;
    if (tid < INF) db = yb[tid] * __ldg(Bg_w + c * INF + tid);

    #pragma unroll
    for (int o = 16; o > 0; o >>= 1) {
        acc += __shfl_down_sync(0xffffffffu, acc, o);
        db  += __shfl_down_sync(0xffffffffu, db,  o);
    }
    if (lane == 0) { sh_sw[warp] = acc; sh_bw[warp] = db; }
    __syncthreads();
    if (tid == 0) {
        sh_s = sh_sw[0] + sh_sw[1] + sh_sw[2] + sh_sw[3]
             + sh_sw[4] + sh_sw[5] + sh_sw[6] + sh_sw[7];
        sh_b = sh_bw[0] + sh_bw[1] + sh_bw[2] + sh_bw[3]
             + sh_bw[4] + sh_bw[5] + sh_bw[6] + sh_bw[7]
             + __ldg(Bg_b + c);
    }
    __syncthreads();
    const float s  = sh_s;
    const float bi = sh_b;

    // ---- 3. stream the plane: 4 chunks x 4 float4/thread ----
#define APPLY(v)                                   \
    do {                                           \
        (v).x = fmaxf(fmaf((v).x, s, bi), 0.f);    \
        (v).y = fmaxf(fmaf((v).y, s, bi), 0.f);    \
        (v).z = fmaxf(fmaf((v).z, s, bi), 0.f);    \
        (v).w = fmaxf(fmaf((v).w, s, bi), 0.f);    \
    } while (0)

    float4 n0, n1, n2, n3;
    #pragma unroll
    for (int k = 0; k < 4; ++k) {
        const int cur = k * 1024 + tid;
        // issue next chunk's loads before this chunk's stores
        if (k < 3) {
            const int nx = cur + 1024;
            n0 = __ldcs(hp + nx);
            n1 = __ldcs(hp + nx + 256);
            n2 = __ldcs(hp + nx + 512);
            n3 = __ldcs(hp + nx + 768);
        }
        APPLY(a0); APPLY(a1); APPLY(a2); APPLY(a3);
        __stcs(op + cur,       a0);
        __stcs(op + cur + 256, a1);
        __stcs(op + cur + 512, a2);
        __stcs(op + cur + 768, a3);
        a0 = n0; a1 = n1; a2 = n2; a3 = n3;
    }
#undef APPLY
}

// ---------------------------------------------------------------------------
// Launch. Input order per metadata: h, y, Wg_w, Wg_b, Bg_w, Bg_b
// Single node, plain 1-D launch, no clusters, no barriers.
// ---------------------------------------------------------------------------
extern "C" void kernel_launch(void* const* d_in, const int* in_sizes, int n_in,
                              void* d_out, int out_size)
{
    const float* h    = (const float*)d_in[0];
    const float* y    = (const float*)d_in[1];
    const float* Wg_w = (const float*)d_in[2];
    const float* Wg_b = (const float*)d_in[3];
    const float* Bg_w = (const float*)d_in[4];
    const float* Bg_b = (const float*)d_in[5];
    float* out = (float*)d_out;

    fused_kernel<<<NBLK, 256>>>(h, y, Wg_w, Wg_b, Bg_w, Bg_b, out);
}